// round 1
// baseline (speedup 1.0000x reference)
#include <cuda_runtime.h>

#define N_NODES  100000
#define N_EDGES  3200000
#define N_GRAPHS 128

// ---------------- scratch (static device globals; no runtime alloc) ----------
__device__ int   g_cnt[N_NODES];
__device__ int   g_rowptr[N_NODES + 1];
__device__ int   g_fill[N_NODES];
__device__ int   g_bsums[128];
__device__ float g_dinv[N_NODES];
__device__ int   g_csr_src[N_EDGES];
__device__ float g_csr_w[N_EDGES];
__device__ float g_bufa[N_NODES * 64];   // aggregation output (16- or 64-wide)
__device__ float g_bufh[N_NODES * 64];   // activations after matmul+relu
__device__ float g_pool[N_GRAPHS * 64];

// ---------------- degree histogram ----------------
__global__ void k_zero_cnt() {
    int i = blockIdx.x * blockDim.x + threadIdx.x;
    if (i < N_NODES) g_cnt[i] = 0;
}

__global__ void k_hist(const int* __restrict__ dst) {
    int i = blockIdx.x * blockDim.x + threadIdx.x;
    if (i < N_EDGES) atomicAdd(&g_cnt[dst[i]], 1);
}

// ---------------- exclusive scan over 100k counts (3 kernels) ----------------
__global__ void k_scan_blocks() {
    __shared__ int s[1024];
    int tid = threadIdx.x;
    int i = blockIdx.x * 1024 + tid;
    int v = (i < N_NODES) ? g_cnt[i] : 0;
    s[tid] = v;
    __syncthreads();
    for (int off = 1; off < 1024; off <<= 1) {
        int t = (tid >= off) ? s[tid - off] : 0;
        __syncthreads();
        s[tid] += t;
        __syncthreads();
    }
    if (i < N_NODES) g_rowptr[i] = s[tid] - v;   // exclusive
    if (tid == 1023) g_bsums[blockIdx.x] = s[1023];
}

__global__ void k_scan_sums(int nb) {
    if (threadIdx.x == 0) {
        int run = 0;
        for (int b = 0; b < nb; b++) { int t = g_bsums[b]; g_bsums[b] = run; run += t; }
    }
}

__global__ void k_scan_add() {
    int tid = threadIdx.x;
    int i = blockIdx.x * 1024 + tid;
    if (i < N_NODES) {
        g_rowptr[i] += g_bsums[blockIdx.x];
        g_dinv[i] = rsqrtf((float)(g_cnt[i] + 1));   // +1 self loop; deg>=1 always
        g_fill[i] = 0;
    }
    if (i == 0) g_rowptr[N_NODES] = N_EDGES;
}

// ---------------- CSR fill (src idx + precomputed norm weight) ----------------
__global__ void k_fill(const int* __restrict__ src, const int* __restrict__ dst) {
    int i = blockIdx.x * blockDim.x + threadIdx.x;
    if (i < N_EDGES) {
        int d = dst[i], s = src[i];
        int pos = g_rowptr[d] + atomicAdd(&g_fill[d], 1);
        g_csr_src[pos] = s;
        g_csr_w[pos] = g_dinv[s] * g_dinv[d];
    }
}

// ---------------- aggregation: 16-wide (layer 1, raw x) ----------------
// warp per node; two half-warps each take alternating edges, combine at end.
__global__ void k_agg16(const float* __restrict__ x) {
    int w = (blockIdx.x * blockDim.x + threadIdx.x) >> 5;
    if (w >= N_NODES) return;
    int lane = threadIdx.x & 31;
    int grp = lane >> 4, c = lane & 15;
    int e0 = g_rowptr[w], e1 = g_rowptr[w + 1];
    float dv = g_dinv[w];
    float a = (grp == 0) ? x[w * 16 + c] * dv * dv : 0.0f;   // self loop
    int e = e0 + grp;
    for (; e + 2 < e1; e += 4) {                              // 2 edges per group per iter
        int   s0 = g_csr_src[e],  s1 = g_csr_src[e + 2];
        float w0 = g_csr_w[e],    w1 = g_csr_w[e + 2];
        float v0 = x[s0 * 16 + c], v1 = x[s1 * 16 + c];
        a += v0 * w0;
        a += v1 * w1;
    }
    for (; e < e1; e += 2) {
        int s = g_csr_src[e];
        a += x[s * 16 + c] * g_csr_w[e];
    }
    a += __shfl_xor_sync(0xffffffffu, a, 16);
    if (grp == 0) g_bufa[w * 16 + c] = a;
}

// ---------------- aggregation: 64-wide (layers 2,3: g_bufh -> g_bufa) --------
__global__ void k_agg64() {
    int w = (blockIdx.x * blockDim.x + threadIdx.x) >> 5;
    if (w >= N_NODES) return;
    int lane = threadIdx.x & 31;
    int e0 = g_rowptr[w], e1 = g_rowptr[w + 1];
    float dv = g_dinv[w];
    const float* base = g_bufh + (size_t)w * 64;
    float dv2 = dv * dv;
    float a0 = base[lane] * dv2;
    float a1 = base[lane + 32] * dv2;
    int e = e0;
    for (; e + 4 <= e1; e += 4) {
        int s0 = g_csr_src[e], s1 = g_csr_src[e + 1];
        int s2 = g_csr_src[e + 2], s3 = g_csr_src[e + 3];
        float w0 = g_csr_w[e], w1 = g_csr_w[e + 1];
        float w2 = g_csr_w[e + 2], w3 = g_csr_w[e + 3];
        const float* p0 = g_bufh + (size_t)s0 * 64;
        const float* p1 = g_bufh + (size_t)s1 * 64;
        const float* p2 = g_bufh + (size_t)s2 * 64;
        const float* p3 = g_bufh + (size_t)s3 * 64;
        float v00 = p0[lane], v01 = p0[lane + 32];
        float v10 = p1[lane], v11 = p1[lane + 32];
        float v20 = p2[lane], v21 = p2[lane + 32];
        float v30 = p3[lane], v31 = p3[lane + 32];
        a0 += v00 * w0; a1 += v01 * w0;
        a0 += v10 * w1; a1 += v11 * w1;
        a0 += v20 * w2; a1 += v21 * w2;
        a0 += v30 * w3; a1 += v31 * w3;
    }
    for (; e < e1; e++) {
        int s = g_csr_src[e];
        float wt = g_csr_w[e];
        const float* p = g_bufh + (size_t)s * 64;
        a0 += p[lane] * wt;
        a1 += p[lane + 32] * wt;
    }
    g_bufa[w * 64 + lane] = a0;
    g_bufa[w * 64 + lane + 32] = a1;
}

// ---------------- matmul + bias + relu: g_bufa [N,K] @ W [K,64] -> g_bufh ----
template <int K>
__global__ void k_mm_relu(const float* __restrict__ Wm, const float* __restrict__ bv) {
    __shared__ float s_in[64 * K];
    int tid = threadIdx.x;           // 256
    int row0 = blockIdx.x * 64;
    int col = tid & 63;
    float wreg[K];
#pragma unroll
    for (int k = 0; k < K; k++) wreg[k] = Wm[k * 64 + col];
    float bias = bv[col];
    int nrows = min(64, N_NODES - row0);
    for (int idx = tid; idx < nrows * K; idx += 256) s_in[idx] = g_bufa[row0 * K + idx];
    __syncthreads();
    int rg = tid >> 6;
    for (int r = rg; r < nrows; r += 4) {
        float acc = bias;
#pragma unroll
        for (int k = 0; k < K; k++) acc += s_in[r * K + k] * wreg[k];
        g_bufh[(row0 + r) * 64 + col] = fmaxf(acc, 0.0f);
    }
}

// ---------------- mean pool per graph (batch is sorted) ----------------------
__global__ void k_pool(const int* __restrict__ batch) {
    int g = blockIdx.x;
    // lower_bound(batch, g)
    int lo = 0, hi = N_NODES;
    while (lo < hi) { int mid = (lo + hi) >> 1; if (batch[mid] < g) lo = mid + 1; else hi = mid; }
    int start = lo;
    lo = start; hi = N_NODES;
    while (lo < hi) { int mid = (lo + hi) >> 1; if (batch[mid] < g + 1) lo = mid + 1; else hi = mid; }
    int end = lo;

    __shared__ float s[4][64];
    int col = threadIdx.x & 63, rg = threadIdx.x >> 6;
    float acc = 0.0f;
    for (int r = start + rg; r < end; r += 4) acc += g_bufh[(size_t)r * 64 + col];
    s[rg][col] = acc;
    __syncthreads();
    if (rg == 0) {
        float t = s[0][col] + s[1][col] + s[2][col] + s[3][col];
        float c = (float)(end - start);
        if (c < 1.0f) c = 1.0f;
        g_pool[g * 64 + col] = t / c;
    }
}

// ---------------- MLP head: pooled[128,64] @ Wf1[64,32] relu @ Wf2[32,1] -----
__global__ void k_head(const float* __restrict__ Wf1, const float* __restrict__ bf1,
                       const float* __restrict__ Wf2, const float* __restrict__ bf2,
                       float* __restrict__ out) {
    int g = threadIdx.x;
    if (g >= N_GRAPHS) return;
    float p[64];
#pragma unroll
    for (int k = 0; k < 64; k++) p[k] = g_pool[g * 64 + k];
    float o = bf2[0];
#pragma unroll 4
    for (int j = 0; j < 32; j++) {
        float hj = bf1[j];
#pragma unroll
        for (int k = 0; k < 64; k++) hj += p[k] * Wf1[k * 32 + j];
        o += fmaxf(hj, 0.0f) * Wf2[j];
    }
    out[g] = o;
}

// ---------------- launch ----------------
extern "C" void kernel_launch(void* const* d_in, const int* in_sizes, int n_in,
                              void* d_out, int out_size) {
    const float* x   = (const float*)d_in[0];
    const int*   ei  = (const int*)d_in[1];
    const int*   src = ei;
    const int*   dst = ei + N_EDGES;
    // d_in[2] = edge_attr (unused by the reference network)
    const int*   batch = (const int*)d_in[3];
    const float* W1 = (const float*)d_in[4];  const float* b1 = (const float*)d_in[5];
    const float* W2 = (const float*)d_in[6];  const float* b2 = (const float*)d_in[7];
    const float* W3 = (const float*)d_in[8];  const float* b3 = (const float*)d_in[9];
    const float* Wf1 = (const float*)d_in[10]; const float* bf1 = (const float*)d_in[11];
    const float* Wf2 = (const float*)d_in[12]; const float* bf2 = (const float*)d_in[13];
    float* out = (float*)d_out;

    const int nb_scan = (N_NODES + 1023) / 1024;       // 98
    const int eb = (N_EDGES + 255) / 256;              // 12500
    const int wb = (N_NODES * 32 + 255) / 256;         // one warp per node
    const int mb = (N_NODES + 63) / 64;                // 64 rows per block

    k_zero_cnt<<<(N_NODES + 255) / 256, 256>>>();
    k_hist<<<eb, 256>>>(dst);
    k_scan_blocks<<<nb_scan, 1024>>>();
    k_scan_sums<<<1, 32>>>(nb_scan);
    k_scan_add<<<nb_scan, 1024>>>();
    k_fill<<<eb, 256>>>(src, dst);

    // layer 1: aggregate raw 16-wide features, then (agg @ W1 + b1).relu
    k_agg16<<<wb, 256>>>(x);
    k_mm_relu<16><<<mb, 256>>>(W1, b1);
    // layer 2
    k_agg64<<<wb, 256>>>();
    k_mm_relu<64><<<mb, 256>>>(W2, b2);
    // layer 3
    k_agg64<<<wb, 256>>>();
    k_mm_relu<64><<<mb, 256>>>(W3, b3);

    k_pool<<<N_GRAPHS, 256>>>(batch);
    k_head<<<1, 128>>>(Wf1, bf1, Wf2, bf2, out);
}